// round 16
// baseline (speedup 1.0000x reference)
#include <cuda_runtime.h>

// CplxGaussianRBF: out[b,c,p,{re,im}] = sum_w exp(-|x[b,c,p]-mu[w]|^2/(2*sd[w])) * w_{re,im}[c,w] + bias
// B=4, C=32, H=W=64 (HW=4096), NW=64.
//
// R16: cross-round fit says dur ~ 10ns per added per-thread instruction with a big
// fixed intercept; two attackable pieces of the intercept:
//  (1) wave quantization: 40 regs -> 6 blocks/SM -> 888+136-block tail wave.
//      __launch_bounds__(256,7) forces <=36 regs -> 7 blocks/SM -> grid 1024 fits
//      in ONE wave (148*7=1036), tail gone, 48->56 theoretical warps/SM.
//  (2) init serialization: full-precision '/' (15-instr Newton) + t<32-only init.
//      Now __fdividef (2 instrs) and 3-way parallel init (ab/cd/wp by separate warps).
// Main loop is R7's proven minimum-instruction core (weight-pair f32x2 packing,
// pure ex2 on MUFU); manual prefetch dropped to stay in the 36-reg budget.

#define CN   32
#define HWN  4096
#define NWN  64

typedef unsigned long long u64t;

__device__ __forceinline__ u64t fma2(u64t a, u64t b, u64t c) {
    u64t d;
    asm("fma.rn.f32x2 %0, %1, %2, %3;" : "=l"(d) : "l"(a), "l"(b), "l"(c));
    return d;
}
__device__ __forceinline__ u64t pack2(float lo, float hi) {
    u64t d;
    asm("mov.b64 %0, {%1, %2};" : "=l"(d) : "f"(lo), "f"(hi));
    return d;
}
__device__ __forceinline__ void unpack2(u64t v, float& lo, float& hi) {
    asm("mov.b64 {%0, %1}, %2;" : "=f"(lo), "=f"(hi) : "l"(v));
}
__device__ __forceinline__ u64t ex2_2(u64t v) {
    float t0, t1;
    unpack2(v, t0, t1);
    float e0, e1;
    asm("ex2.approx.f32 %0, %1;" : "=f"(e0) : "f"(t0));
    asm("ex2.approx.f32 %0, %1;" : "=f"(e1) : "f"(t1));
    return pack2(e0, e1);
}

__global__ __launch_bounds__(256, 7)
void cplx_rbf_kernel(
    const float* __restrict__ xr, const float* __restrict__ xi,
    const float* __restrict__ wr, const float* __restrict__ wi,
    const float* __restrict__ br, const float* __restrict__ bi,
    const float* __restrict__ mur, const float* __restrict__ mui,
    const float* __restrict__ sd,
    float* __restrict__ out)
{
    // Per weight-pair j (weights 2j, 2j+1):
    //   s_ab[j] = {A0, A1, B0, B1}; s_cd[j] = {C0, C1, D0, D1}; s_wp[j] = {wr0, wr1, wi0, wi1}
    __shared__ __align__(16) float s_ab[NWN * 2];
    __shared__ __align__(16) float s_cd[NWN * 2];
    __shared__ __align__(16) float s_wp[NWN * 2];

    const int t  = threadIdx.x;
    const int bc = blockIdx.x >> 3;           // (b*C + c) slice index (8 blocks/slice)
    const int c  = bc & (CN - 1);

    // 3-way parallel init: warps 0, 1, 2 build ab, cd, wp independently.
    if (t < NWN / 2) {
        const int w0 = 2 * t, w1 = 2 * t + 1;
        const float cf0 = __fdividef(-0.7213475204444817f, sd[w0]);  // -log2(e)/(2*sd)
        const float cf1 = __fdividef(-0.7213475204444817f, sd[w1]);
        reinterpret_cast<float4*>(s_ab)[t] =
            make_float4(cf0, cf1, -2.0f * cf0 * mur[w0], -2.0f * cf1 * mur[w1]);
    } else if (t < NWN) {
        const int j = t - NWN / 2;
        const int w0 = 2 * j, w1 = 2 * j + 1;
        const float cf0 = __fdividef(-0.7213475204444817f, sd[w0]);
        const float cf1 = __fdividef(-0.7213475204444817f, sd[w1]);
        const float mr0 = mur[w0], mi0 = mui[w0];
        const float mr1 = mur[w1], mi1 = mui[w1];
        reinterpret_cast<float4*>(s_cd)[j] =
            make_float4(-2.0f * cf0 * mi0, -2.0f * cf1 * mi1,
                        cf0 * fmaf(mr0, mr0, mi0 * mi0),
                        cf1 * fmaf(mr1, mr1, mi1 * mi1));
    } else if (t < NWN + NWN / 2) {
        const int j = t - NWN;
        const int w0 = 2 * j, w1 = 2 * j + 1;
        reinterpret_cast<float4*>(s_wp)[j] =
            make_float4(wr[c * NWN + w0], wr[c * NWN + w1],
                        wi[c * NWN + w0], wi[c * NWN + w1]);
    }
    __syncthreads();

    const int p0   = ((blockIdx.x & 7) << 9) + (t << 1);   // 2 pixels per thread
    const int base = bc * HWN;

    const float2 x_r = *reinterpret_cast<const float2*>(xr + base + p0);
    const float2 x_i = *reinterpret_cast<const float2*>(xi + base + p0);

    // duplicated per-pixel packed values
    const u64t xr0d = pack2(x_r.x, x_r.x);
    const u64t xi0d = pack2(x_i.x, x_i.x);
    const u64t xr1d = pack2(x_r.y, x_r.y);
    const u64t xi1d = pack2(x_i.y, x_i.y);
    const float n0 = fmaf(x_r.x, x_r.x, x_i.x * x_i.x);
    const float n1 = fmaf(x_r.y, x_r.y, x_i.y * x_i.y);
    const u64t n0d = pack2(n0, n0);
    const u64t n1d = pack2(n1, n1);

    u64t accr0 = 0ULL, acci0 = 0ULL;   // {sum even w, sum odd w}
    u64t accr1 = 0ULL, acci1 = 0ULL;

    const ulonglong2* ab2 = reinterpret_cast<const ulonglong2*>(s_ab);
    const ulonglong2* cd2 = reinterpret_cast<const ulonglong2*>(s_cd);
    const ulonglong2* wp2 = reinterpret_cast<const ulonglong2*>(s_wp);

#pragma unroll
    for (int j = 0; j < NWN / 2; j++) {
        const ulonglong2 ab = ab2[j];   // .x = {A0,A1},   .y = {B0,B1}
        const ulonglong2 cd = cd2[j];   // .x = {C0,C1},   .y = {D0,D1}
        const ulonglong2 wp = wp2[j];   // .x = {wr0,wr1}, .y = {wi0,wi1}

        u64t e0 = fma2(ab.x, n0d, cd.y);   // A*n + D
        u64t e1 = fma2(ab.x, n1d, cd.y);
        e0 = fma2(ab.y, xr0d, e0);         // + B*xr
        e1 = fma2(ab.y, xr1d, e1);
        e0 = fma2(cd.x, xi0d, e0);         // + C*xi
        e1 = fma2(cd.x, xi1d, e1);

        const u64t g0 = ex2_2(e0);
        const u64t g1 = ex2_2(e1);

        accr0 = fma2(g0, wp.x, accr0);
        acci0 = fma2(g0, wp.y, acci0);
        accr1 = fma2(g1, wp.x, accr1);
        acci1 = fma2(g1, wp.y, acci1);
    }

    float a, b2;
    const float brc = br[c];
    const float bic = bi[c];

    float4 o;
    unpack2(accr0, a, b2);  o.x = a + b2 + brc;   // pixel p0   real
    unpack2(acci0, a, b2);  o.y = a + b2 + bic;   // pixel p0   imag
    unpack2(accr1, a, b2);  o.z = a + b2 + brc;   // pixel p0+1 real
    unpack2(acci1, a, b2);  o.w = a + b2 + bic;   // pixel p0+1 imag
    *reinterpret_cast<float4*>(out + (size_t)(base + p0) * 2) = o;
}

extern "C" void kernel_launch(void* const* d_in, const int* in_sizes, int n_in,
                              void* d_out, int out_size)
{
    const float* xr  = (const float*)d_in[0];  // x_real  (4,32,64,64)
    const float* xi  = (const float*)d_in[1];  // x_imag
    const float* wr  = (const float*)d_in[2];  // w_real  (32,64)
    const float* wi  = (const float*)d_in[3];  // w_imag
    const float* br  = (const float*)d_in[4];  // b_real  (1,32,1)
    const float* bi  = (const float*)d_in[5];  // b_imag
    const float* mur = (const float*)d_in[6];  // mu_real (64)
    const float* mui = (const float*)d_in[7];  // mu_imag (64)
    const float* sd  = (const float*)d_in[8];  // stddev  (64)
    float* out = (float*)d_out;                // (4,32,64,64,2)

    // 4*32*4096 pixels / (256 threads * 2 pixels) = 1024 blocks, one full wave at 7 blocks/SM
    cplx_rbf_kernel<<<1024, 256>>>(xr, xi, wr, wi, br, bi, mur, mui, sd, out);
}